// round 3
// baseline (speedup 1.0000x reference)
#include <cuda_runtime.h>
#include <math.h>

// Problem constants
#define B 16
#define N_TOK 196          // 14*14
#define BN_ROWS (B * N_TOK)   // 3136
#define D 128
#define Q_ROWS 65536
#define INV_T 5.0f         // 1/0.2
#define M_PAD 3200         // 25 * 128

// Output layout in d_out (float): [0]=loss, [1..3136]=pos_sim, [3137..]=neg_sim (3136 x 65536)
#define POS_OFF 1
#define NEG_OFF (1 + BN_ROWS)

// Scratch (zero-initialized at module load; pad rows of g_q stay 0 forever)
__device__ float g_q[M_PAD * D];
__device__ float g_k[BN_ROWS * D];
__device__ float g_queue[Q_ROWS * D];
__device__ float g_rowsum[M_PAD];

// ---------------------------------------------------------------------------
__global__ void zero_kernel() {
    int i = blockIdx.x * blockDim.x + threadIdx.x;
    if (i < M_PAD) g_rowsum[i] = 0.0f;
}

// Normalize q (dense_features_1) and k (dense_features_2): one warp per row.
__global__ void norm_qk_kernel(const float* __restrict__ f1, const float* __restrict__ f2) {
    int w = (blockIdx.x * blockDim.x + threadIdx.x) >> 5;
    int lane = threadIdx.x & 31;
    if (w >= BN_ROWS) return;
    size_t base = (size_t)w * D;

    float4 v = ((const float4*)(f1 + base))[lane];
    float s = v.x * v.x + v.y * v.y + v.z * v.z + v.w * v.w;
    #pragma unroll
    for (int o = 16; o; o >>= 1) s += __shfl_xor_sync(0xffffffffu, s, o);
    float inv = 1.0f / sqrtf(fmaxf(s, 1e-24f));
    float4 r; r.x = v.x * inv; r.y = v.y * inv; r.z = v.z * inv; r.w = v.w * inv;
    ((float4*)(g_q + base))[lane] = r;

    float4 u = ((const float4*)(f2 + base))[lane];
    float t = u.x * u.x + u.y * u.y + u.z * u.z + u.w * u.w;
    #pragma unroll
    for (int o = 16; o; o >>= 1) t += __shfl_xor_sync(0xffffffffu, t, o);
    float invk = 1.0f / sqrtf(fmaxf(t, 1e-24f));
    float4 rk; rk.x = u.x * invk; rk.y = u.y * invk; rk.z = u.z * invk; rk.w = u.w * invk;
    ((float4*)(g_k + base))[lane] = rk;
}

// Normalize the queue: one warp per row.
__global__ void norm_queue_kernel(const float* __restrict__ qin) {
    int w = (blockIdx.x * blockDim.x + threadIdx.x) >> 5;
    int lane = threadIdx.x & 31;
    if (w >= Q_ROWS) return;
    size_t base = (size_t)w * D;
    float4 v = ((const float4*)(qin + base))[lane];
    float s = v.x * v.x + v.y * v.y + v.z * v.z + v.w * v.w;
    #pragma unroll
    for (int o = 16; o; o >>= 1) s += __shfl_xor_sync(0xffffffffu, s, o);
    float inv = 1.0f / sqrtf(fmaxf(s, 1e-24f));
    float4 r; r.x = v.x * inv; r.y = v.y * inv; r.z = v.z * inv; r.w = v.w * inv;
    ((float4*)(g_queue + base))[lane] = r;
}

// pos_sim[row] = max_m ( q[row] . k[batch(row), m] ) * (1/T). One warp per query row.
__global__ void pos_kernel(float* __restrict__ out_pos) {
    int w = (blockIdx.x * blockDim.x + threadIdx.x) >> 5;
    int lane = threadIdx.x & 31;
    if (w >= BN_ROWS) return;
    int b = w / N_TOK;
    float4 qv = ((const float4*)(g_q + (size_t)w * D))[lane];
    const float* kb = g_k + (size_t)b * N_TOK * D;
    float best = -1e30f;
    for (int m = 0; m < N_TOK; m++) {
        float4 kv = ((const float4*)(kb + (size_t)m * D))[lane];
        float d = qv.x * kv.x + qv.y * kv.y + qv.z * kv.z + qv.w * kv.w;
        #pragma unroll
        for (int o = 16; o; o >>= 1) d += __shfl_xor_sync(0xffffffffu, d, o);
        best = fmaxf(best, d);
    }
    if (lane == 0) out_pos[w] = best * INV_T;
}

// ---------------------------------------------------------------------------
// neg GEMM: neg[m][n] = (g_q[m] . g_queue[n]) * INV_T, plus per-row sum(exp).
// 128x128 block tile, BK=16, 256 threads, 8x8 per thread (2x2 groups of 4x4).
#define BM 128
#define BNT 128
#define BK 16
#define LDS_STRIDE 132   // 132*4 = 528 bytes, 16B-aligned rows for LDS.128

__global__ __launch_bounds__(256, 2)
void gemm_neg_kernel(float* __restrict__ neg) {
    __shared__ float As[BK][LDS_STRIDE];
    __shared__ float Bs[BK][LDS_STRIDE];
    __shared__ float srow[BM];

    int tid = threadIdx.x;
    int tx = tid & 15;        // 0..15 -> column group
    int ty = tid >> 4;        // 0..15 -> row group
    int m0 = blockIdx.y * BM;
    int n0 = blockIdx.x * BNT;

    int lr = tid >> 2;        // 0..63 (row within half-tile)
    int lc = tid & 3;         // 0..3  (float4 within 16 k-cols)

    float acc[2][2][4][4];
    #pragma unroll
    for (int a = 0; a < 2; a++)
        #pragma unroll
        for (int b = 0; b < 2; b++)
            #pragma unroll
            for (int i = 0; i < 4; i++)
                #pragma unroll
                for (int j = 0; j < 4; j++) acc[a][b][i][j] = 0.0f;

    for (int k0 = 0; k0 < D; k0 += BK) {
        #pragma unroll
        for (int h = 0; h < 2; h++) {
            int m = lr + 64 * h;
            float4 v = *(const float4*)(g_q + (size_t)(m0 + m) * D + k0 + lc * 4);
            As[lc * 4 + 0][m] = v.x; As[lc * 4 + 1][m] = v.y;
            As[lc * 4 + 2][m] = v.z; As[lc * 4 + 3][m] = v.w;
            float4 w = *(const float4*)(g_queue + (size_t)(n0 + m) * D + k0 + lc * 4);
            Bs[lc * 4 + 0][m] = w.x; Bs[lc * 4 + 1][m] = w.y;
            Bs[lc * 4 + 2][m] = w.z; Bs[lc * 4 + 3][m] = w.w;
        }
        __syncthreads();

        #pragma unroll
        for (int kk = 0; kk < BK; kk++) {
            float4 a0 = *(const float4*)(&As[kk][ty * 4]);
            float4 a1 = *(const float4*)(&As[kk][ty * 4 + 64]);
            float4 b0 = *(const float4*)(&Bs[kk][tx * 4]);
            float4 b1 = *(const float4*)(&Bs[kk][tx * 4 + 64]);
            float av[2][4] = {{a0.x, a0.y, a0.z, a0.w}, {a1.x, a1.y, a1.z, a1.w}};
            float bv[2][4] = {{b0.x, b0.y, b0.z, b0.w}, {b1.x, b1.y, b1.z, b1.w}};
            #pragma unroll
            for (int ra = 0; ra < 2; ra++)
                #pragma unroll
                for (int cb = 0; cb < 2; cb++)
                    #pragma unroll
                    for (int i = 0; i < 4; i++)
                        #pragma unroll
                        for (int j = 0; j < 4; j++)
                            acc[ra][cb][i][j] += av[ra][i] * bv[cb][j];
        }
        __syncthreads();
    }

    // epilogue: scale by 1/T, store (scalar — d_out neg base is only 4B aligned),
    // and accumulate exp row sums.
    for (int i = tid; i < BM; i += 256) srow[i] = 0.0f;
    __syncthreads();

    #pragma unroll
    for (int ra = 0; ra < 2; ra++) {
        #pragma unroll
        for (int i = 0; i < 4; i++) {
            int mloc = ra * 64 + ty * 4 + i;
            int m = m0 + mloc;
            if (m < BN_ROWS) {
                float rsum = 0.0f;
                float* rowp = neg + (size_t)m * Q_ROWS + n0;
                #pragma unroll
                for (int cb = 0; cb < 2; cb++) {
                    float* p = rowp + cb * 64 + tx * 4;
                    #pragma unroll
                    for (int j = 0; j < 4; j++) {
                        float v = acc[ra][cb][i][j] * INV_T;
                        __stcs(p + j, v);
                        rsum += __expf(v);
                    }
                }
                atomicAdd(&srow[mloc], rsum);
            }
        }
    }
    __syncthreads();
    for (int i = tid; i < BM; i += 256) {
        int m = m0 + i;
        if (m < BN_ROWS) atomicAdd(&g_rowsum[m], srow[i]);
    }
}

// ---------------------------------------------------------------------------
// loss = mean( log(exp(pos) + rowsum) - pos )
__global__ void loss_kernel(const float* __restrict__ pos, float* __restrict__ out_loss) {
    __shared__ float sred[1024];
    float acc = 0.0f;
    for (int i = threadIdx.x; i < BN_ROWS; i += 1024) {
        float p = pos[i];
        acc += logf(g_rowsum[i] + expf(p)) - p;
    }
    sred[threadIdx.x] = acc;
    __syncthreads();
    for (int s = 512; s; s >>= 1) {
        if (threadIdx.x < s) sred[threadIdx.x] += sred[threadIdx.x + s];
        __syncthreads();
    }
    if (threadIdx.x == 0) out_loss[0] = sred[0] / (float)BN_ROWS;
}

// ---------------------------------------------------------------------------
extern "C" void kernel_launch(void* const* d_in, const int* in_sizes, int n_in,
                              void* d_out, int out_size) {
    const float* f1 = (const float*)d_in[0];   // dense_features_1
    const float* f2 = (const float*)d_in[1];   // dense_features_2
    // d_in[2], d_in[3] (backbone features) are unused by the reference.
    const float* qu = (const float*)d_in[4];   // queue
    float* out = (float*)d_out;

    zero_kernel<<<7, 512>>>();
    norm_qk_kernel<<<BN_ROWS / 8, 256>>>(f1, f2);
    norm_queue_kernel<<<Q_ROWS / 8, 256>>>(qu);
    pos_kernel<<<BN_ROWS / 8, 256>>>(out + POS_OFF);
    dim3 grid(Q_ROWS / BNT, M_PAD / BM);  // (512, 25)
    gemm_neg_kernel<<<grid, 256>>>(out + NEG_OFF);
    loss_kernel<<<1, 1024>>>(out + POS_OFF, out);
}

// round 5
// speedup vs baseline: 1.7984x; 1.7984x over previous
#include <cuda_runtime.h>
#include <cuda_fp16.h>
#include <math.h>
#include <stdint.h>

// ---------------- problem constants ----------------
#define N_TOK 196
#define BN_ROWS 3136
#define DIM 128
#define Q_ROWS 65536
#define INV_T 5.0f
#define M_PAD 3200          // 25 * 128

#define POS_OFF 1
#define NEG_OFF (1 + BN_ROWS)

// ---------------- device globals (zero-init; pad rows of g_qh/g_ql stay 0) --
__device__ float  g_q[BN_ROWS * DIM];     // normalized q (fp32, for pos)
__device__ float  g_k[BN_ROWS * DIM];     // normalized k (fp32, for pos)
__device__ __half g_qh[M_PAD * DIM];      // q hi split
__device__ __half g_ql[M_PAD * DIM];      // q lo split
__device__ __half g_uh[Q_ROWS * DIM];     // queue hi split
__device__ __half g_ul[Q_ROWS * DIM];     // queue lo split
__device__ float  g_rowsum[M_PAD];

// ---------------- helpers ----------------
__device__ __forceinline__ uint32_t split2(float a, float b, uint32_t& lo) {
    __half ha = __float2half_rn(a), hb = __float2half_rn(b);
    __half la = __float2half_rn(a - __half2float(ha));
    __half lb = __float2half_rn(b - __half2float(hb));
    __half2 h = __halves2half2(ha, hb);
    __half2 l = __halves2half2(la, lb);
    lo = *reinterpret_cast<uint32_t*>(&l);
    return *reinterpret_cast<uint32_t*>(&h);
}

#define MMA(c, a, b) asm volatile( \
    "mma.sync.aligned.m16n8k16.row.col.f32.f16.f16.f32 " \
    "{%0,%1,%2,%3},{%4,%5,%6,%7},{%8,%9},{%0,%1,%2,%3};" \
    : "+f"((c)[0]), "+f"((c)[1]), "+f"((c)[2]), "+f"((c)[3]) \
    : "r"((a)[0]), "r"((a)[1]), "r"((a)[2]), "r"((a)[3]), \
      "r"((b)[0]), "r"((b)[1]))

// ---------------------------------------------------------------------------
__global__ void zero_kernel() {
    int i = blockIdx.x * blockDim.x + threadIdx.x;
    if (i < M_PAD) g_rowsum[i] = 0.0f;
}

// Normalize q/k, write fp32 (for pos) and fp16 hi/lo splits of q (for GEMM).
__global__ void norm_qk_kernel(const float* __restrict__ f1, const float* __restrict__ f2) {
    int w = (blockIdx.x * blockDim.x + threadIdx.x) >> 5;
    int lane = threadIdx.x & 31;
    if (w >= BN_ROWS) return;
    size_t base = (size_t)w * DIM;

    float4 v = ((const float4*)(f1 + base))[lane];
    float s = v.x * v.x + v.y * v.y + v.z * v.z + v.w * v.w;
    #pragma unroll
    for (int o = 16; o; o >>= 1) s += __shfl_xor_sync(0xffffffffu, s, o);
    float inv = 1.0f / sqrtf(fmaxf(s, 1e-24f));
    float4 r; r.x = v.x * inv; r.y = v.y * inv; r.z = v.z * inv; r.w = v.w * inv;
    ((float4*)(g_q + base))[lane] = r;
    uint32_t l0, l1;
    uint32_t h0 = split2(r.x, r.y, l0);
    uint32_t h1 = split2(r.z, r.w, l1);
    ((uint2*)(g_qh + base))[lane] = make_uint2(h0, h1);
    ((uint2*)(g_ql + base))[lane] = make_uint2(l0, l1);

    float4 u = ((const float4*)(f2 + base))[lane];
    float t = u.x * u.x + u.y * u.y + u.z * u.z + u.w * u.w;
    #pragma unroll
    for (int o = 16; o; o >>= 1) t += __shfl_xor_sync(0xffffffffu, t, o);
    float ik = 1.0f / sqrtf(fmaxf(t, 1e-24f));
    float4 rk; rk.x = u.x * ik; rk.y = u.y * ik; rk.z = u.z * ik; rk.w = u.w * ik;
    ((float4*)(g_k + base))[lane] = rk;
}

// Normalize queue, write fp16 hi/lo splits only.
__global__ void norm_queue_kernel(const float* __restrict__ qin) {
    int w = (blockIdx.x * blockDim.x + threadIdx.x) >> 5;
    int lane = threadIdx.x & 31;
    if (w >= Q_ROWS) return;
    size_t base = (size_t)w * DIM;
    float4 v = ((const float4*)(qin + base))[lane];
    float s = v.x * v.x + v.y * v.y + v.z * v.z + v.w * v.w;
    #pragma unroll
    for (int o = 16; o; o >>= 1) s += __shfl_xor_sync(0xffffffffu, s, o);
    float inv = 1.0f / sqrtf(fmaxf(s, 1e-24f));
    uint32_t l0, l1;
    uint32_t h0 = split2(v.x * inv, v.y * inv, l0);
    uint32_t h1 = split2(v.z * inv, v.w * inv, l1);
    ((uint2*)(g_uh + base))[lane] = make_uint2(h0, h1);
    ((uint2*)(g_ul + base))[lane] = make_uint2(l0, l1);
}

// pos: one warp per query, 4 keys per iteration.
__global__ void pos_kernel(float* __restrict__ out_pos) {
    int w = (blockIdx.x * blockDim.x + threadIdx.x) >> 5;
    int lane = threadIdx.x & 31;
    if (w >= BN_ROWS) return;
    int b = w / N_TOK;
    float4 qv = ((const float4*)(g_q + (size_t)w * DIM))[lane];
    const float4* kb = (const float4*)(g_k + (size_t)b * N_TOK * DIM);
    float best = -1e30f;
    for (int m = 0; m < N_TOK; m += 4) {
        const float4* p = kb + (size_t)m * 32;
        float4 a = p[lane], c = p[32 + lane], e = p[64 + lane], f = p[96 + lane];
        float d0 = qv.x * a.x + qv.y * a.y + qv.z * a.z + qv.w * a.w;
        float d1 = qv.x * c.x + qv.y * c.y + qv.z * c.z + qv.w * c.w;
        float d2 = qv.x * e.x + qv.y * e.y + qv.z * e.z + qv.w * e.w;
        float d3 = qv.x * f.x + qv.y * f.y + qv.z * f.z + qv.w * f.w;
        #pragma unroll
        for (int o = 16; o; o >>= 1) {
            d0 += __shfl_xor_sync(0xffffffffu, d0, o);
            d1 += __shfl_xor_sync(0xffffffffu, d1, o);
            d2 += __shfl_xor_sync(0xffffffffu, d2, o);
            d3 += __shfl_xor_sync(0xffffffffu, d3, o);
        }
        best = fmaxf(best, fmaxf(fmaxf(d0, d1), fmaxf(d2, d3)));
    }
    if (lane == 0) out_pos[w] = best * INV_T;
}

// ---------------------------------------------------------------------------
// neg GEMM via mma.sync (HMMA) with 3-term fp16 error-compensated split.
// Block tile 128x128, 8 warps (2x4), warp tile 64x32, BK=64 in 2 phases.
// Smem rows: per 8-word k-group, word w stored at pos (w%4)*2 + w/4 so that
// fragment pairs (k, k+8) are adjacent -> single LDS.64 per fragment pair.
#define STRW 40   // words per smem row (32 data + 8 pad): conflict-free LDS.64

#define SMEM_WORDS (4 * 128 * STRW + 128)
#define SMEM_BYTES (SMEM_WORDS * 4)

__global__ __launch_bounds__(256, 2)
void gemm_neg_kernel(float* __restrict__ neg) {
    extern __shared__ __align__(16) uint32_t sm[];
    uint32_t* sAh = sm;
    uint32_t* sAl = sm + 128 * STRW;
    uint32_t* sBh = sm + 2 * 128 * STRW;
    uint32_t* sBl = sm + 3 * 128 * STRW;
    float* srow = (float*)(sm + 4 * 128 * STRW);

    int tid = threadIdx.x;
    int lane = tid & 31, wid = tid >> 5;
    int g = lane >> 2, tg = lane & 3;
    int warp_m = wid & 1, warp_n = wid >> 1;
    int m0 = blockIdx.y * 128;
    size_t n0 = (size_t)blockIdx.x * 128;

    float acc[4][4][4];
    #pragma unroll
    for (int i = 0; i < 4; i++)
        #pragma unroll
        for (int j = 0; j < 4; j++)
            #pragma unroll
            for (int c = 0; c < 4; c++) acc[i][j][c] = 0.0f;

    #pragma unroll
    for (int ph = 0; ph < 2; ph++) {
        int k0 = ph * 64;
        // ---- fill: 1024 uint4 per array, 256 threads x 4 iters ----
        #pragma unroll
        for (int it = 0; it < 4; it++) {
            int idx = tid + it * 256;
            int row = idx >> 3, u = idx & 7;
            int dof = row * STRW + (u >> 1) * 8 + (u & 1);
            uint4 va = *((const uint4*)(g_qh + (size_t)(m0 + row) * DIM + k0) + u);
            sAh[dof] = va.x; sAh[dof + 2] = va.y; sAh[dof + 4] = va.z; sAh[dof + 6] = va.w;
            uint4 vb = *((const uint4*)(g_ql + (size_t)(m0 + row) * DIM + k0) + u);
            sAl[dof] = vb.x; sAl[dof + 2] = vb.y; sAl[dof + 4] = vb.z; sAl[dof + 6] = vb.w;
            uint4 vc = *((const uint4*)(g_uh + (n0 + row) * DIM + k0) + u);
            sBh[dof] = vc.x; sBh[dof + 2] = vc.y; sBh[dof + 4] = vc.z; sBh[dof + 6] = vc.w;
            uint4 vd = *((const uint4*)(g_ul + (n0 + row) * DIM + k0) + u);
            sBl[dof] = vd.x; sBl[dof + 2] = vd.y; sBl[dof + 4] = vd.z; sBl[dof + 6] = vd.w;
        }
        __syncthreads();

        // ---- mma: 4 k-steps of 16 ----
        #pragma unroll
        for (int s = 0; s < 4; s++) {
            int so = s * 8 + 2 * tg;
            uint32_t Ah[4][4], Bh[4][2], Bl[4][2];
            #pragma unroll
            for (int i = 0; i < 4; i++) {
                int r = (warp_m * 64 + i * 16 + g) * STRW + so;
                uint2 x = *(const uint2*)&sAh[r];
                uint2 y = *(const uint2*)&sAh[r + 8 * STRW];
                Ah[i][0] = x.x; Ah[i][2] = x.y;   // a0 (k..), a2 (k+8..)
                Ah[i][1] = y.x; Ah[i][3] = y.y;   // a1, a3 (row +8)
            }
            #pragma unroll
            for (int j = 0; j < 4; j++) {
                int r = (warp_n * 32 + j * 8 + g) * STRW + so;
                uint2 b = *(const uint2*)&sBh[r];
                Bh[j][0] = b.x; Bh[j][1] = b.y;
                uint2 c = *(const uint2*)&sBl[r];
                Bl[j][0] = c.x; Bl[j][1] = c.y;
            }
            #pragma unroll
            for (int i = 0; i < 4; i++)
                #pragma unroll
                for (int j = 0; j < 4; j++) {
                    MMA(acc[i][j], Ah[i], Bh[j]);
                    MMA(acc[i][j], Ah[i], Bl[j]);
                }
            uint32_t Al[4][4];
            #pragma unroll
            for (int i = 0; i < 4; i++) {
                int r = (warp_m * 64 + i * 16 + g) * STRW + so;
                uint2 x = *(const uint2*)&sAl[r];
                uint2 y = *(const uint2*)&sAl[r + 8 * STRW];
                Al[i][0] = x.x; Al[i][2] = x.y;
                Al[i][1] = y.x; Al[i][3] = y.y;
            }
            #pragma unroll
            for (int i = 0; i < 4; i++)
                #pragma unroll
                for (int j = 0; j < 4; j++)
                    MMA(acc[i][j], Al[i], Bh[j]);
        }
        __syncthreads();
    }

    // ---- epilogue: scale, store (scalar: neg base is 4B-misaligned), expsum
    for (int i = tid; i < 128; i += 256) srow[i] = 0.0f;
    __syncthreads();

    #pragma unroll
    for (int i = 0; i < 4; i++) {
        #pragma unroll
        for (int h = 0; h < 2; h++) {
            int rl = warp_m * 64 + i * 16 + g + h * 8;
            int gm = m0 + rl;
            if (gm < BN_ROWS) {
                float* rp = neg + (size_t)gm * Q_ROWS + n0 + warp_n * 32 + tg * 2;
                float es = 0.0f;
                #pragma unroll
                for (int j = 0; j < 4; j++) {
                    float v0 = acc[i][j][h * 2] * INV_T;
                    float v1 = acc[i][j][h * 2 + 1] * INV_T;
                    __stcs(rp + j * 8, v0);
                    __stcs(rp + j * 8 + 1, v1);
                    es += __expf(v0) + __expf(v1);
                }
                atomicAdd(&srow[rl], es);
            }
        }
    }
    __syncthreads();
    for (int i = tid; i < 128; i += 256) {
        int gm = m0 + i;
        if (gm < BN_ROWS) atomicAdd(&g_rowsum[gm], srow[i]);
    }
}

// ---------------------------------------------------------------------------
__global__ void loss_kernel(const float* __restrict__ pos, float* __restrict__ out_loss) {
    __shared__ float sred[1024];
    float acc = 0.0f;
    for (int i = threadIdx.x; i < BN_ROWS; i += 1024) {
        float p = pos[i];
        acc += logf(g_rowsum[i] + expf(p)) - p;
    }
    sred[threadIdx.x] = acc;
    __syncthreads();
    for (int s = 512; s; s >>= 1) {
        if (threadIdx.x < s) sred[threadIdx.x] += sred[threadIdx.x + s];
        __syncthreads();
    }
    if (threadIdx.x == 0) out_loss[0] = sred[0] / (float)BN_ROWS;
}

// ---------------------------------------------------------------------------
extern "C" void kernel_launch(void* const* d_in, const int* in_sizes, int n_in,
                              void* d_out, int out_size) {
    const float* f1 = (const float*)d_in[0];
    const float* f2 = (const float*)d_in[1];
    const float* qu = (const float*)d_in[4];
    float* out = (float*)d_out;

    cudaFuncSetAttribute(gemm_neg_kernel, cudaFuncAttributeMaxDynamicSharedMemorySize, SMEM_BYTES);

    zero_kernel<<<7, 512>>>();
    norm_qk_kernel<<<BN_ROWS / 8, 256>>>(f1, f2);
    norm_queue_kernel<<<Q_ROWS / 8, 256>>>(qu);
    pos_kernel<<<BN_ROWS / 8, 256>>>(out + POS_OFF);
    dim3 grid(Q_ROWS / 128, M_PAD / 128);   // (512, 25)
    gemm_neg_kernel<<<grid, 256, SMEM_BYTES>>>(out + NEG_OFF);
    loss_kernel<<<1, 1024>>>(out + POS_OFF, out);
}

// round 6
// speedup vs baseline: 2.3356x; 1.2987x over previous
#include <cuda_runtime.h>
#include <cuda_fp16.h>
#include <math.h>
#include <stdint.h>

// ---------------- problem constants ----------------
#define N_TOK 196
#define BN_ROWS 3136
#define DIM 128
#define Q_ROWS 65536
#define INV_T 5.0f
#define M_PAD 3200          // 25 * 128

#define POS_OFF 1
#define NEG_OFF (1 + BN_ROWS)

// ---------------- device globals (zero-init; pad rows of g_qh/g_ql stay 0) --
__device__ float  g_q[BN_ROWS * DIM];
__device__ float  g_k[BN_ROWS * DIM];
__device__ __half g_qh[M_PAD * DIM];
__device__ __half g_ql[M_PAD * DIM];
__device__ __half g_uh[Q_ROWS * DIM];
__device__ __half g_ul[Q_ROWS * DIM];
__device__ float  g_rowsum[M_PAD];

// ---------------- helpers ----------------
__device__ __forceinline__ uint32_t split2(float a, float b, uint32_t& lo) {
    __half ha = __float2half_rn(a), hb = __float2half_rn(b);
    __half la = __float2half_rn(a - __half2float(ha));
    __half lb = __float2half_rn(b - __half2float(hb));
    __half2 h = __halves2half2(ha, hb);
    __half2 l = __halves2half2(la, lb);
    lo = *reinterpret_cast<uint32_t*>(&l);
    return *reinterpret_cast<uint32_t*>(&h);
}

__device__ __forceinline__ uint32_t smem_u32(const void* p) {
    uint32_t a;
    asm("{ .reg .u64 t; cvta.to.shared.u64 t, %1; cvt.u32.u64 %0, t; }" : "=r"(a) : "l"(p));
    return a;
}

#define MMA(c, a, b) asm volatile( \
    "mma.sync.aligned.m16n8k16.row.col.f32.f16.f16.f32 " \
    "{%0,%1,%2,%3},{%4,%5,%6,%7},{%8,%9},{%0,%1,%2,%3};" \
    : "+f"((c)[0]), "+f"((c)[1]), "+f"((c)[2]), "+f"((c)[3]) \
    : "r"((a)[0]), "r"((a)[1]), "r"((a)[2]), "r"((a)[3]), \
      "r"((b)[0]), "r"((b)[1]))

#define LDSM_X4(r, addr) asm volatile( \
    "ldmatrix.sync.aligned.m8n8.x4.shared.b16 {%0,%1,%2,%3}, [%4];" \
    : "=r"((r)[0]), "=r"((r)[1]), "=r"((r)[2]), "=r"((r)[3]) : "r"(addr))

#define LDSM_X2(r, addr) asm volatile( \
    "ldmatrix.sync.aligned.m8n8.x2.shared.b16 {%0,%1}, [%2];" \
    : "=r"((r)[0]), "=r"((r)[1]) : "r"(addr))

#define CP_ASYNC16(dst, src) asm volatile( \
    "cp.async.cg.shared.global [%0], [%1], 16;" :: "r"(dst), "l"(src))

// ---------------------------------------------------------------------------
__global__ void zero_kernel() {
    int i = blockIdx.x * blockDim.x + threadIdx.x;
    if (i < M_PAD) g_rowsum[i] = 0.0f;
}

__global__ void norm_qk_kernel(const float* __restrict__ f1, const float* __restrict__ f2) {
    int w = (blockIdx.x * blockDim.x + threadIdx.x) >> 5;
    int lane = threadIdx.x & 31;
    if (w >= BN_ROWS) return;
    size_t base = (size_t)w * DIM;

    float4 v = ((const float4*)(f1 + base))[lane];
    float s = v.x * v.x + v.y * v.y + v.z * v.z + v.w * v.w;
    #pragma unroll
    for (int o = 16; o; o >>= 1) s += __shfl_xor_sync(0xffffffffu, s, o);
    float inv = 1.0f / sqrtf(fmaxf(s, 1e-24f));
    float4 r; r.x = v.x * inv; r.y = v.y * inv; r.z = v.z * inv; r.w = v.w * inv;
    ((float4*)(g_q + base))[lane] = r;
    uint32_t l0, l1;
    uint32_t h0 = split2(r.x, r.y, l0);
    uint32_t h1 = split2(r.z, r.w, l1);
    ((uint2*)(g_qh + base))[lane] = make_uint2(h0, h1);
    ((uint2*)(g_ql + base))[lane] = make_uint2(l0, l1);

    float4 u = ((const float4*)(f2 + base))[lane];
    float t = u.x * u.x + u.y * u.y + u.z * u.z + u.w * u.w;
    #pragma unroll
    for (int o = 16; o; o >>= 1) t += __shfl_xor_sync(0xffffffffu, t, o);
    float ik = 1.0f / sqrtf(fmaxf(t, 1e-24f));
    float4 rk; rk.x = u.x * ik; rk.y = u.y * ik; rk.z = u.z * ik; rk.w = u.w * ik;
    ((float4*)(g_k + base))[lane] = rk;
}

__global__ void norm_queue_kernel(const float* __restrict__ qin) {
    int w = (blockIdx.x * blockDim.x + threadIdx.x) >> 5;
    int lane = threadIdx.x & 31;
    if (w >= Q_ROWS) return;
    size_t base = (size_t)w * DIM;
    float4 v = ((const float4*)(qin + base))[lane];
    float s = v.x * v.x + v.y * v.y + v.z * v.z + v.w * v.w;
    #pragma unroll
    for (int o = 16; o; o >>= 1) s += __shfl_xor_sync(0xffffffffu, s, o);
    float inv = 1.0f / sqrtf(fmaxf(s, 1e-24f));
    uint32_t l0, l1;
    uint32_t h0 = split2(v.x * inv, v.y * inv, l0);
    uint32_t h1 = split2(v.z * inv, v.w * inv, l1);
    ((uint2*)(g_uh + base))[lane] = make_uint2(h0, h1);
    ((uint2*)(g_ul + base))[lane] = make_uint2(l0, l1);
}

__global__ void pos_kernel(float* __restrict__ out_pos) {
    int w = (blockIdx.x * blockDim.x + threadIdx.x) >> 5;
    int lane = threadIdx.x & 31;
    if (w >= BN_ROWS) return;
    int b = w / N_TOK;
    float4 qv = ((const float4*)(g_q + (size_t)w * DIM))[lane];
    const float4* kb = (const float4*)(g_k + (size_t)b * N_TOK * DIM);
    float best = -1e30f;
    for (int m = 0; m < N_TOK; m += 4) {
        const float4* p = kb + (size_t)m * 32;
        float4 a = p[lane], c = p[32 + lane], e = p[64 + lane], f = p[96 + lane];
        float d0 = qv.x * a.x + qv.y * a.y + qv.z * a.z + qv.w * a.w;
        float d1 = qv.x * c.x + qv.y * c.y + qv.z * c.z + qv.w * c.w;
        float d2 = qv.x * e.x + qv.y * e.y + qv.z * e.z + qv.w * e.w;
        float d3 = qv.x * f.x + qv.y * f.y + qv.z * f.z + qv.w * f.w;
        #pragma unroll
        for (int o = 16; o; o >>= 1) {
            d0 += __shfl_xor_sync(0xffffffffu, d0, o);
            d1 += __shfl_xor_sync(0xffffffffu, d1, o);
            d2 += __shfl_xor_sync(0xffffffffu, d2, o);
            d3 += __shfl_xor_sync(0xffffffffu, d3, o);
        }
        best = fmaxf(best, fmaxf(fmaxf(d0, d1), fmaxf(d2, d3)));
    }
    if (lane == 0) out_pos[w] = best * INV_T;
}

// ---------------------------------------------------------------------------
// neg GEMM: 128x128 block, 8 warps (2x4), warp tile 64x32, BK=64 x 2 phases.
// Smem: 4 arrays [128 rows x 128B] SW128-swizzled; chunk' = chunk ^ (row&7).
// Fills via cp.async, fragment loads via ldmatrix.
#define ARR_BYTES (128 * 128)
#define SMEM_BYTES (4 * ARR_BYTES + 512)

__global__ __launch_bounds__(256, 2)
void gemm_neg_kernel(float* __restrict__ neg) {
    extern __shared__ __align__(1024) char smem[];
    uint32_t sb = smem_u32(smem);
    uint32_t sAh = sb;
    uint32_t sAl = sb + ARR_BYTES;
    uint32_t sBh = sb + 2 * ARR_BYTES;
    uint32_t sBl = sb + 3 * ARR_BYTES;
    float* srow = (float*)(smem + 4 * ARR_BYTES);

    int tid = threadIdx.x;
    int lane = tid & 31, wid = tid >> 5;
    int g = lane >> 2, tg = lane & 3;
    int warp_m = wid & 1, warp_n = wid >> 1;
    int m0 = blockIdx.y * 128;
    size_t n0 = (size_t)blockIdx.x * 128;

    // cp.async fill indices: this thread covers rows fr, fr+64 with chunk fu (x2 arrays)
    int fr = tid >> 2;           // 0..63
    int fu0 = (tid & 3) << 1;    // 0,2,4,6

    // ldmatrix addresses (A: x4 over 16 rows x 32B; B: x2 over 8 rows x 32B)
    int a_row = warp_m * 64 + (lane & 15);
    int a_ch = lane >> 4;                 // 0/1
    uint32_t aAh_base = sAh + a_row * 128;
    uint32_t aAl_base = sAl + a_row * 128;
    int a_sw = a_row & 7;
    int b_row = warp_n * 32 + (lane & 7);
    int b_ch = (lane >> 3) & 1;
    uint32_t aBh_base = sBh + b_row * 128;
    uint32_t aBl_base = sBl + b_row * 128;
    int b_sw = b_row & 7;

    float acc[4][4][4];
    #pragma unroll
    for (int i = 0; i < 4; i++)
        #pragma unroll
        for (int j = 0; j < 4; j++)
            #pragma unroll
            for (int c = 0; c < 4; c++) acc[i][j][c] = 0.0f;

    #pragma unroll
    for (int ph = 0; ph < 2; ph++) {
        int k0 = ph * 64;
        // ---- fill via cp.async: 16 x 16B per thread ----
        #pragma unroll
        for (int rr = 0; rr < 2; rr++) {
            int row = fr + rr * 64;
            #pragma unroll
            for (int uu = 0; uu < 2; uu++) {
                int u = fu0 + uu;
                uint32_t doff = row * 128 + ((u ^ (row & 7)) << 4);
                const __half* srcA = g_qh + (size_t)(m0 + row) * DIM + k0 + u * 8;
                CP_ASYNC16(sAh + doff, srcA);
                CP_ASYNC16(sAl + doff, g_ql + (size_t)(m0 + row) * DIM + k0 + u * 8);
                CP_ASYNC16(sBh + doff, g_uh + (n0 + row) * DIM + k0 + u * 8);
                CP_ASYNC16(sBl + doff, g_ul + (n0 + row) * DIM + k0 + u * 8);
            }
        }
        asm volatile("cp.async.commit_group;" ::: "memory");
        asm volatile("cp.async.wait_group 0;" ::: "memory");
        __syncthreads();

        // ---- mma: 4 k-steps of 16 ----
        #pragma unroll
        for (int s = 0; s < 4; s++) {
            uint32_t Bh[4][2], Bl[4][2];
            #pragma unroll
            for (int j = 0; j < 4; j++) {
                int ch = (2 * s + b_ch) ^ b_sw;
                uint32_t off = j * 8 * 128 + (ch << 4);
                LDSM_X2(Bh[j], aBh_base + off);
                LDSM_X2(Bl[j], aBl_base + off);
            }
            #pragma unroll
            for (int i = 0; i < 4; i++) {
                int ch = (2 * s + a_ch) ^ a_sw;
                uint32_t off = i * 16 * 128 + (ch << 4);
                uint32_t Af[4];
                LDSM_X4(Af, aAh_base + off);
                #pragma unroll
                for (int j = 0; j < 4; j++) MMA(acc[i][j], Af, Bh[j]);
                #pragma unroll
                for (int j = 0; j < 4; j++) MMA(acc[i][j], Af, Bl[j]);
                LDSM_X4(Af, aAl_base + off);
                #pragma unroll
                for (int j = 0; j < 4; j++) MMA(acc[i][j], Af, Bh[j]);
            }
        }
        if (ph == 0) __syncthreads();
    }

    // ---- epilogue: scale, scalar stores (neg base 4B-misaligned), expsum ----
    for (int i = tid; i < 128; i += 256) srow[i] = 0.0f;
    __syncthreads();

    #pragma unroll
    for (int i = 0; i < 4; i++) {
        #pragma unroll
        for (int h = 0; h < 2; h++) {
            int rl = warp_m * 64 + i * 16 + g + h * 8;
            int gm = m0 + rl;
            if (gm < BN_ROWS) {
                float* rp = neg + (size_t)gm * Q_ROWS + n0 + warp_n * 32 + tg * 2;
                float es = 0.0f;
                #pragma unroll
                for (int j = 0; j < 4; j++) {
                    float v0 = acc[i][j][h * 2] * INV_T;
                    float v1 = acc[i][j][h * 2 + 1] * INV_T;
                    __stcs(rp + j * 8, v0);
                    __stcs(rp + j * 8 + 1, v1);
                    es += __expf(v0) + __expf(v1);
                }
                atomicAdd(&srow[rl], es);
            }
        }
    }
    __syncthreads();
    for (int i = tid; i < 128; i += 256) {
        int gm = m0 + i;
        if (gm < BN_ROWS) atomicAdd(&g_rowsum[gm], srow[i]);
    }
}

// ---------------------------------------------------------------------------
__global__ void loss_kernel(const float* __restrict__ pos, float* __restrict__ out_loss) {
    __shared__ float sred[1024];
    float acc = 0.0f;
    for (int i = threadIdx.x; i < BN_ROWS; i += 1024) {
        float p = pos[i];
        acc += logf(g_rowsum[i] + expf(p)) - p;
    }
    sred[threadIdx.x] = acc;
    __syncthreads();
    for (int s = 512; s; s >>= 1) {
        if (threadIdx.x < s) sred[threadIdx.x] += sred[threadIdx.x + s];
        __syncthreads();
    }
    if (threadIdx.x == 0) out_loss[0] = sred[0] / (float)BN_ROWS;
}

// ---------------------------------------------------------------------------
extern "C" void kernel_launch(void* const* d_in, const int* in_sizes, int n_in,
                              void* d_out, int out_size) {
    const float* f1 = (const float*)d_in[0];
    const float* f2 = (const float*)d_in[1];
    const float* qu = (const float*)d_in[4];
    float* out = (float*)d_out;

    cudaFuncSetAttribute(gemm_neg_kernel, cudaFuncAttributeMaxDynamicSharedMemorySize, SMEM_BYTES);

    zero_kernel<<<7, 512>>>();
    norm_qk_kernel<<<BN_ROWS / 8, 256>>>(f1, f2);
    norm_queue_kernel<<<Q_ROWS / 8, 256>>>(qu);
    pos_kernel<<<BN_ROWS / 8, 256>>>(out + POS_OFF);
    dim3 grid(Q_ROWS / 128, M_PAD / 128);   // (512, 25)
    gemm_neg_kernel<<<grid, 256, SMEM_BYTES>>>(out + NEG_OFF);
    loss_kernel<<<1, 1024>>>(out + POS_OFF, out);
}